// round 2
// baseline (speedup 1.0000x reference)
#include <cuda_runtime.h>
#include <cuda_bf16.h>

// Problem constants (fixed shapes per reference)
#define B_ROWS   4096
#define N_COLS   64
#define BIN      256
#define TOT      (N_COLS * BIN)   // 16384

// Scratch for per-row partial sums (no allocation allowed in kernel_launch)
__device__ float g_row_partials[B_ROWS];

// One block per row. 8 warps; each warp owns one column (256 bins) per
// iteration, 8 iterations cover the 64 columns. Each lane holds 8 bins in
// registers: z[0..3] = bins [lane*4, lane*4+4), z[4..7] = bins [128+lane*4, ...).
__global__ __launch_bounds__(256, 8)
void obs_loss_kernel(const float* __restrict__ logits,
                     const float* __restrict__ gumbel,
                     const int* __restrict__ mask,      // jax bool -> int32
                     const int* __restrict__ targets)
{
    const int row  = blockIdx.x;
    const int wid  = threadIdx.x >> 5;
    const int lane = threadIdx.x & 31;

    const float* lrow = logits + (size_t)row * TOT;
    const float* grow = gumbel + (size_t)row * TOT;

    float acc = 0.0f;

    #pragma unroll
    for (int it = 0; it < 8; ++it) {
        const int col  = it * 8 + wid;
        const int base = col * BIN;

        // Coalesced: lanes cover [base, base+128) and [base+128, base+256)
        float4 l0 = *reinterpret_cast<const float4*>(lrow + base + lane * 4);
        float4 l1 = *reinterpret_cast<const float4*>(lrow + base + 128 + lane * 4);
        float4 g0 = *reinterpret_cast<const float4*>(grow + base + lane * 4);
        float4 g1 = *reinterpret_cast<const float4*>(grow + base + 128 + lane * 4);

        float z[8];
        z[0] = l0.x + g0.x;  z[1] = l0.y + g0.y;
        z[2] = l0.z + g0.z;  z[3] = l0.w + g0.w;
        z[4] = l1.x + g1.x;  z[5] = l1.y + g1.y;
        z[6] = l1.z + g1.z;  z[7] = l1.w + g1.w;

        // Column max (TAU = 1, so no divide)
        float m = z[0];
        #pragma unroll
        for (int i = 1; i < 8; ++i) m = fmaxf(m, z[i]);
        #pragma unroll
        for (int off = 16; off > 0; off >>= 1)
            m = fmaxf(m, __shfl_xor_sync(0xFFFFFFFFu, m, off));

        // Sum of exp(z - m)
        float s = 0.0f;
        #pragma unroll
        for (int i = 0; i < 8; ++i) s += __expf(z[i] - m);
        #pragma unroll
        for (int off = 16; off > 0; off >>= 1)
            s += __shfl_xor_sync(0xFFFFFFFFu, s, off);

        const float lse = m + __logf(s);

        // Only the lane owning the target bin contributes.
        const int t     = targets[row * N_COLS + col];
        const int half  = t >> 7;          // 0: first 128 bins, 1: second
        const int tl    = t & 127;
        const int olane = tl >> 2;
        const int slot  = (tl & 3) + half * 4;

        if (lane == olane) {
            const int mk = mask[(size_t)row * TOT + base + t];
            if (!mk) acc += (lse - z[slot]);   // -(z_t - lse)
        }
    }

    // Warp reduce, then block reduce to one per-row partial.
    #pragma unroll
    for (int off = 16; off > 0; off >>= 1)
        acc += __shfl_xor_sync(0xFFFFFFFFu, acc, off);

    __shared__ float sacc[8];
    if (lane == 0) sacc[wid] = acc;
    __syncthreads();

    if (threadIdx.x == 0) {
        float s = 0.0f;
        #pragma unroll
        for (int i = 0; i < 8; ++i) s += sacc[i];
        g_row_partials[row] = s;
    }
}

__global__ __launch_bounds__(1024)
void reduce_kernel(float* __restrict__ out)
{
    __shared__ float sh[1024];
    float s = 0.0f;
    for (int i = threadIdx.x; i < B_ROWS; i += 1024)
        s += g_row_partials[i];
    sh[threadIdx.x] = s;
    __syncthreads();
    #pragma unroll
    for (int stride = 512; stride > 0; stride >>= 1) {
        if (threadIdx.x < stride) sh[threadIdx.x] += sh[threadIdx.x + stride];
        __syncthreads();
    }
    if (threadIdx.x == 0) {
        const float loss = sh[0];
        out[0] = loss;
        out[1] = loss / ((float)B_ROWS * 0.69314718055994530942f);
    }
}

extern "C" void kernel_launch(void* const* d_in, const int* in_sizes, int n_in,
                              void* d_out, int out_size)
{
    const float* logits  = (const float*)d_in[0];
    const float* gumbel  = (const float*)d_in[1];
    const int*   mask    = (const int*)d_in[2];
    const int*   targets = (const int*)d_in[3];
    // d_in[4] = bin_size scalar (256), fixed — unused.
    (void)in_sizes; (void)n_in; (void)out_size;

    float* out = (float*)d_out;

    obs_loss_kernel<<<B_ROWS, 256>>>(logits, gumbel, mask, targets);
    reduce_kernel<<<1, 1024>>>(out);
}

// round 3
// speedup vs baseline: 1.0336x; 1.0336x over previous
#include <cuda_runtime.h>
#include <cuda_bf16.h>

// Problem constants (fixed shapes per reference)
#define B_ROWS   4096
#define N_COLS   64
#define BIN      256
#define TOT      (N_COLS * BIN)   // 16384

// Scratch: per-row partials + last-block ticket counter (no allocs allowed).
__device__ float g_row_partials[B_ROWS];
__device__ unsigned int g_ticket = 0;   // reset to 0 by the last block each launch

// One block per row. 8 warps; each warp owns one column (256 bins) per
// iteration, 8 iterations cover the 64 columns. Each lane holds 8 bins in
// registers. The LAST block to finish reduces all row partials and writes out.
__global__ __launch_bounds__(256, 8)
void obs_loss_kernel(const float* __restrict__ logits,
                     const float* __restrict__ gumbel,
                     const int* __restrict__ mask,      // jax bool -> int32
                     const int* __restrict__ targets,
                     float* __restrict__ out)
{
    const int row  = blockIdx.x;
    const int wid  = threadIdx.x >> 5;
    const int lane = threadIdx.x & 31;

    const float* lrow = logits + (size_t)row * TOT;
    const float* grow = gumbel + (size_t)row * TOT;

    float acc = 0.0f;

    #pragma unroll
    for (int it = 0; it < 8; ++it) {
        const int col  = it * 8 + wid;
        const int base = col * BIN;

        // Streaming loads (no reuse): lanes cover [base, base+128) and [+128, +256)
        float4 l0 = __ldcs(reinterpret_cast<const float4*>(lrow + base + lane * 4));
        float4 l1 = __ldcs(reinterpret_cast<const float4*>(lrow + base + 128 + lane * 4));
        float4 g0 = __ldcs(reinterpret_cast<const float4*>(grow + base + lane * 4));
        float4 g1 = __ldcs(reinterpret_cast<const float4*>(grow + base + 128 + lane * 4));

        float z[8];
        z[0] = l0.x + g0.x;  z[1] = l0.y + g0.y;
        z[2] = l0.z + g0.z;  z[3] = l0.w + g0.w;
        z[4] = l1.x + g1.x;  z[5] = l1.y + g1.y;
        z[6] = l1.z + g1.z;  z[7] = l1.w + g1.w;

        // Column max (TAU = 1, so no divide)
        float m = z[0];
        #pragma unroll
        for (int i = 1; i < 8; ++i) m = fmaxf(m, z[i]);
        #pragma unroll
        for (int off = 16; off > 0; off >>= 1)
            m = fmaxf(m, __shfl_xor_sync(0xFFFFFFFFu, m, off));

        // Sum of exp(z - m)
        float s = 0.0f;
        #pragma unroll
        for (int i = 0; i < 8; ++i) s += __expf(z[i] - m);
        #pragma unroll
        for (int off = 16; off > 0; off >>= 1)
            s += __shfl_xor_sync(0xFFFFFFFFu, s, off);

        const float lse = m + __logf(s);

        // Only the lane owning the target bin contributes.
        const int t     = targets[row * N_COLS + col];
        const int half  = t >> 7;          // 0: first 128 bins, 1: second
        const int tl    = t & 127;
        const int olane = tl >> 2;
        const int slot  = (tl & 3) + half * 4;

        if (lane == olane) {
            const int mk = mask[(size_t)row * TOT + base + t];
            if (!mk) acc += (lse - z[slot]);   // -(z_t - lse)
        }
    }

    // Warp reduce, then block reduce to one per-row partial.
    #pragma unroll
    for (int off = 16; off > 0; off >>= 1)
        acc += __shfl_xor_sync(0xFFFFFFFFu, acc, off);

    __shared__ float sacc[8];
    __shared__ bool  s_last;
    if (lane == 0) sacc[wid] = acc;
    __syncthreads();

    if (threadIdx.x == 0) {
        float s = 0.0f;
        #pragma unroll
        for (int i = 0; i < 8; ++i) s += sacc[i];
        g_row_partials[row] = s;
        __threadfence();                                   // publish partial
        unsigned int t = atomicAdd(&g_ticket, 1u);
        s_last = (t == (unsigned int)(gridDim.x - 1));
    }
    __syncthreads();

    // Last block to arrive performs the final deterministic reduction.
    if (s_last) {
        float s = 0.0f;
        for (int i = threadIdx.x; i < B_ROWS; i += 256)
            s += g_row_partials[i];
        #pragma unroll
        for (int off = 16; off > 0; off >>= 1)
            s += __shfl_xor_sync(0xFFFFFFFFu, s, off);
        if (lane == 0) sacc[wid] = s;
        __syncthreads();
        if (threadIdx.x == 0) {
            float loss = 0.0f;
            #pragma unroll
            for (int i = 0; i < 8; ++i) loss += sacc[i];
            out[0] = loss;
            out[1] = loss / ((float)B_ROWS * 0.69314718055994530942f);
            g_ticket = 0;                                  // reset for next replay
        }
    }
}

extern "C" void kernel_launch(void* const* d_in, const int* in_sizes, int n_in,
                              void* d_out, int out_size)
{
    const float* logits  = (const float*)d_in[0];
    const float* gumbel  = (const float*)d_in[1];
    const int*   mask    = (const int*)d_in[2];
    const int*   targets = (const int*)d_in[3];
    // d_in[4] = bin_size scalar (256), fixed — unused.
    (void)in_sizes; (void)n_in; (void)out_size;

    obs_loss_kernel<<<B_ROWS, 256>>>(logits, gumbel, mask, targets, (float*)d_out);
}